// round 9
// baseline (speedup 1.0000x reference)
#include <cuda_runtime.h>

// FastECT: per-(batch,bin,theta) histogram + cumsum over bins.
// N=200000 pts (D=3), T=128 thetas, R=128 bins, B=64 batches, batch sorted.
//
// R9: the RMW chain is the limiter (issue pinned ~46% across occ 22-50%).
//  (a) ~32% of updates clamp to bin 0/127 (nh~N(0,1)) -> counted in
//      REGISTERS (r0/r127), folded into the flush cumsum. Removes the
//      same-address serialized chains entirely.
//  (b) interior updates alternate between TWO statically-declared smem
//      sub-histograms HA/HB (even/odd point) -> ptxas can prove
//      non-aliasing -> two independent LDS/IADD/STS chains in flight.
// Layout per hist: u8, 4 bins per word per thread: word=(bin>>2)*128+t ->
// bank t%32 for any bin => conflict-free RMW/flush/zero. Thread t owns
// theta t => race-free, no atomics in the hot loop.
// Bin math in packed f32x2 (FFMA2), bit-identical rounding.
// cumsum is linear => flush cumsum(partial) via f32 atomicAdd (exact).

#define TT 128
#define RR 128
#define NBLK 888     // 148 SMs * 6 resident, single balanced wave
#define TILE 256     // >= max points/block (225) -> 1 stage pass/segment

typedef unsigned int       u32;
typedef unsigned char      u8;
typedef unsigned long long u64;

__device__ __forceinline__ int lower_bound_i32(const int* __restrict__ a, int n, int key) {
    int lo = 0, hi = n;
    while (lo < hi) {
        int mid = (lo + hi) >> 1;
        if (a[mid] < key) lo = mid + 1; else hi = mid;
    }
    return lo;
}

// packed f32x2 helpers (sm_103a): same per-lane rounding as scalar chain
__device__ __forceinline__ u64 pack2(float lo, float hi) {
    u64 r; asm("mov.b64 %0, {%1, %2};" : "=l"(r) : "f"(lo), "f"(hi)); return r;
}
__device__ __forceinline__ void unpack2(u64 v, float& lo, float& hi) {
    asm("mov.b64 {%0, %1}, %2;" : "=f"(lo), "=f"(hi) : "l"(v));
}
__device__ __forceinline__ u64 mul2(u64 a, u64 b) {
    u64 r; asm("mul.rn.f32x2 %0, %1, %2;" : "=l"(r) : "l"(a), "l"(b)); return r;
}
__device__ __forceinline__ u64 add2(u64 a, u64 b) {
    u64 r; asm("add.rn.f32x2 %0, %1, %2;" : "=l"(r) : "l"(a), "l"(b)); return r;
}
__device__ __forceinline__ u64 fma2(u64 a, u64 b, u64 c) {
    u64 r; asm("fma.rn.f32x2 %0, %1, %2, %3;" : "=l"(r) : "l"(a), "l"(b), "l"(c)); return r;
}

__global__ void __launch_bounds__(256)
k_zero(float* __restrict__ out, int n4) {
    int i = blockIdx.x * blockDim.x + threadIdx.x;
    if (i < n4) ((float4*)out)[i] = make_float4(0.f, 0.f, 0.f, 0.f);
}

__global__ void __launch_bounds__(128, 6)
k_hist(const float* __restrict__ x, const float* __restrict__ v,
       const int* __restrict__ batch, int n, float* __restrict__ out) {
    // static shared -> ptxas proves HA/HB (and stage) pairwise non-aliasing
    __shared__ u8 HA[RR * TT];
    __shared__ u8 HB[RR * TT];
    __shared__ float SX[TILE], SY[TILE], SZ[TILE];
    __shared__ int seg_end_sh;

    const int t = threadIdx.x;
    const int g = blockIdx.x;
    u8* __restrict__ hA = HA + (t << 2);         // per-thread word bases
    u8* __restrict__ hB = HB + (t << 2);

    const int lo = (int)(((long long)g)     * n / NBLK);
    const int hi = (int)(((long long)g + 1) * n / NBLK);

    const float v0 = v[t];
    const float v1 = v[TT + t];
    const float v2 = v[2 * TT + t];
    const u64 v0p = pack2(v0, v0), v1p = pack2(v1, v1), v2p = pack2(v2, v2);
    const u64 onep = pack2(1.0f, 1.0f), c64p = pack2(64.0f, 64.0f);

    // zero both 16KB histograms (conflict-free uint4 stores)
    {
        uint4* a = (uint4*)HA; uint4* b = (uint4*)HB;
        for (int i = t; i < (RR * TT) / 16; i += 128) {
            a[i] = make_uint4(0u, 0u, 0u, 0u);
            b[i] = make_uint4(0u, 0u, 0u, 0u);
        }
    }

    int pos = lo;
    while (pos < hi) {
        if (t == 0) {
            int b = batch[pos];
            seg_end_sh = min(hi, lower_bound_i32(batch, n, b + 1));
        }
        __syncthreads();
        const int seg_end = seg_end_sh;
        const int b = batch[pos];                // uniform broadcast

        int r0 = 0, r127 = 0;                    // register clamp-bin counts

        for (int base = pos; base < seg_end; base += TILE) {
            const int m = min(TILE, seg_end - base);
            for (int p = t; p < m; p += 128) {
                const float* src = x + (size_t)(base + p) * 3;
                SX[p] = src[0]; SY[p] = src[1]; SZ[p] = src[2];
            }
            __syncthreads();

            int k = 0;
            for (; k + 4 <= m; k += 4) {
                ulonglong2 X = *(const ulonglong2*)(SX + k);
                ulonglong2 Y = *(const ulonglong2*)(SY + k);
                ulonglong2 Z = *(const ulonglong2*)(SZ + k);
                u64 nhA = fma2(Z.x, v2p, fma2(Y.x, v1p, mul2(X.x, v0p)));
                u64 nhB = fma2(Z.y, v2p, fma2(Y.y, v1p, mul2(X.y, v0p)));
                u64 fA  = mul2(add2(nhA, onep), c64p);
                u64 fB  = mul2(add2(nhB, onep), c64p);
                float f0, f1, f2, f3;
                unpack2(fA, f0, f1);
                unpack2(fB, f2, f3);
                int i0 = __float2int_rd(f0), i1 = __float2int_rd(f1);
                int i2 = __float2int_rd(f2), i3 = __float2int_rd(f3);
                // clamp bins -> registers (no smem, no dependent chains)
                r0   += (i0 < 1) + (i1 < 1) + (i2 < 1) + (i3 < 1);
                r127 += (i0 > 126) + (i1 > 126) + (i2 > 126) + (i3 > 126);
                // interior -> alternate sub-hists (provably independent)
                if (i0 >= 1 && i0 <= 126) {
                    u8* a = hA + (i0 >> 2) * 512 + (i0 & 3); *a = (u8)(*a + 1);
                }
                if (i1 >= 1 && i1 <= 126) {
                    u8* a = hB + (i1 >> 2) * 512 + (i1 & 3); *a = (u8)(*a + 1);
                }
                if (i2 >= 1 && i2 <= 126) {
                    u8* a = hA + (i2 >> 2) * 512 + (i2 & 3); *a = (u8)(*a + 1);
                }
                if (i3 >= 1 && i3 <= 126) {
                    u8* a = hB + (i3 >> 2) * 512 + (i3 & 3); *a = (u8)(*a + 1);
                }
            }
            for (; k < m; ++k) {
                float nh = fmaf(SZ[k], v2, fmaf(SY[k], v1, __fmul_rn(SX[k], v0)));
                float f  = __fmul_rn(__fadd_rn(nh, 1.0f), 64.0f);
                int i0 = __float2int_rd(f);
                r0   += (i0 < 1);
                r127 += (i0 > 126);
                if (i0 >= 1 && i0 <= 126) {
                    u8* a = hA + (i0 >> 2) * 512 + (i0 & 3); *a = (u8)(*a + 1);
                }
            }
            __syncthreads();
        }

        // flush: cumsum(HA+HB partial, + r0/r127) += out[b][bin][t]
        {
            int acc = r0;                        // bin 0 lives in registers
            u32* wa = (u32*)HA;
            u32* wb = (u32*)HB;
            float* dst = out + ((size_t)b * RR) * TT + t;
#pragma unroll
            for (int bin4 = 0; bin4 < RR / 4; ++bin4) {
                u32 a = wa[bin4 * 128 + t];
                u32 c = wb[bin4 * 128 + t];
                wa[bin4 * 128 + t] = 0u;         // rezero for next segment
                wb[bin4 * 128 + t] = 0u;
                acc += (int)(a & 255u) + (int)(c & 255u);
                atomicAdd(dst + (bin4 * 4 + 0) * TT, (float)acc);
                acc += (int)((a >> 8) & 255u) + (int)((c >> 8) & 255u);
                atomicAdd(dst + (bin4 * 4 + 1) * TT, (float)acc);
                acc += (int)((a >> 16) & 255u) + (int)((c >> 16) & 255u);
                atomicAdd(dst + (bin4 * 4 + 2) * TT, (float)acc);
                acc += (int)(a >> 24) + (int)(c >> 24);
                if (bin4 == RR / 4 - 1) acc += r127;   // bin 127 registers
                atomicAdd(dst + (bin4 * 4 + 3) * TT, (float)acc);
            }
        }
        pos = seg_end;
        __syncthreads();                         // protect stage/hist reuse
    }
}

extern "C" void kernel_launch(void* const* d_in, const int* in_sizes, int n_in,
                              void* d_out, int out_size) {
    const float* x     = (const float*)d_in[0];   // [200000, 3]
    const float* v     = (const float*)d_in[1];   // [3, 128]
    const int*   batch = (const int*)d_in[2];     // [200000], sorted
    const int n = in_sizes[2];

    float* out = (float*)d_out;                   // [64, 128, 128]
    const int n4 = out_size / 4;

    k_zero<<<(n4 + 255) / 256, 256>>>(out, n4);
    k_hist<<<NBLK, 128>>>(x, v, batch, n, out);
}

// round 10
// speedup vs baseline: 1.1634x; 1.1634x over previous
#include <cuda_runtime.h>

// FastECT: per-(batch,bin,theta) histogram + cumsum over bins.
// N=200000 pts (D=3), T=128 thetas, R=128 bins, B=64 batches, batch sorted.
//
// R10 = R8 structure (best known) + branch-free instruction cuts:
//  - even/odd points go UNCONDITIONALLY to two static smem hists HA/HB:
//    ptxas proves non-aliasing -> the two u8 RMW chains interleave (2x MLP).
//    (R9 showed the dual-hist idea works but branches around it cost ~7us.)
//  - f = fma(nh, 64, 64) == (nh+1)*64 bit-identically (exact pow2 scaling).
//  - clamp via __float2uint_rz (neg -> 0, floor for f>=0) + min(u,127):
//    identical bins, 1 fewer op each.
// Layout per hist: u8, 4 bins per 32-bit word per thread:
//   word = (bin>>2)*128 + t -> bank t%32 for any bin => RMW/flush/zero all
//   conflict-free. Thread t owns theta t => race-free, no hot atomics.
// cumsum linear => flush cumsum(HA+HB) straight into d_out via f32
// atomicAdd (exact integer adds, deterministic).

#define TT 128
#define RR 128
#define NBLK 888     // 148 SMs * 6 resident, single balanced wave
#define TILE 256     // points staged per tile (SoA)

typedef unsigned int       u32;
typedef unsigned char      u8;
typedef unsigned long long u64;

__device__ __forceinline__ int lower_bound_i32(const int* __restrict__ a, int n, int key) {
    int lo = 0, hi = n;
    while (lo < hi) {
        int mid = (lo + hi) >> 1;
        if (a[mid] < key) lo = mid + 1; else hi = mid;
    }
    return lo;
}

// packed f32x2 helpers (sm_103a): same per-lane rounding as scalar chain
__device__ __forceinline__ u64 pack2(float lo, float hi) {
    u64 r; asm("mov.b64 %0, {%1, %2};" : "=l"(r) : "f"(lo), "f"(hi)); return r;
}
__device__ __forceinline__ void unpack2(u64 v, float& lo, float& hi) {
    asm("mov.b64 {%0, %1}, %2;" : "=f"(lo), "=f"(hi) : "l"(v));
}
__device__ __forceinline__ u64 mul2(u64 a, u64 b) {
    u64 r; asm("mul.rn.f32x2 %0, %1, %2;" : "=l"(r) : "l"(a), "l"(b)); return r;
}
__device__ __forceinline__ u64 fma2(u64 a, u64 b, u64 c) {
    u64 r; asm("fma.rn.f32x2 %0, %1, %2, %3;" : "=l"(r) : "l"(a), "l"(b), "l"(c)); return r;
}

// bin = clip(floor(f), 0, 127) for f = 64*nh + 64:
// cvt.rzi.u32 saturates negatives to 0, floors positives; then min with 127.
__device__ __forceinline__ u32 bin_clamp(float f) {
    return min(__float2uint_rz(f), 127u);
}

__global__ void __launch_bounds__(256)
k_zero(float* __restrict__ out, int n4) {
    int i = blockIdx.x * blockDim.x + threadIdx.x;
    if (i < n4) ((float4*)out)[i] = make_float4(0.f, 0.f, 0.f, 0.f);
}

__global__ void __launch_bounds__(128, 6)
k_hist(const float* __restrict__ x, const float* __restrict__ v,
       const int* __restrict__ batch, int n, float* __restrict__ out) {
    __shared__ u8 HA[RR * TT];                   // static -> non-aliasing
    __shared__ u8 HB[RR * TT];
    __shared__ float SX[TILE], SY[TILE], SZ[TILE];
    __shared__ int seg_end_sh;

    const int t = threadIdx.x;
    const int g = blockIdx.x;
    u8* __restrict__ hA = HA + (t << 2);         // per-thread word bases
    u8* __restrict__ hB = HB + (t << 2);

    const int lo = (int)(((long long)g)     * n / NBLK);
    const int hi = (int)(((long long)g + 1) * n / NBLK);

    const float v0 = v[t];
    const float v1 = v[TT + t];
    const float v2 = v[2 * TT + t];
    const u64 v0p = pack2(v0, v0), v1p = pack2(v1, v1), v2p = pack2(v2, v2);
    const u64 c64p = pack2(64.0f, 64.0f);

    // zero both 16KB histograms (conflict-free uint4 stores)
    {
        uint4* a = (uint4*)HA; uint4* b = (uint4*)HB;
        for (int i = t; i < (RR * TT) / 16; i += 128) {
            a[i] = make_uint4(0u, 0u, 0u, 0u);
            b[i] = make_uint4(0u, 0u, 0u, 0u);
        }
    }

    int pos = lo;
    while (pos < hi) {
        if (t == 0) {
            int b = batch[pos];
            seg_end_sh = min(hi, lower_bound_i32(batch, n, b + 1));
        }
        __syncthreads();
        const int seg_end = seg_end_sh;
        const int b = batch[pos];                // uniform broadcast

        for (int base = pos; base < seg_end; base += TILE) {
            const int m = min(TILE, seg_end - base);
            for (int p = t; p < m; p += 128) {
                const float* src = x + (size_t)(base + p) * 3;
                SX[p] = src[0]; SY[p] = src[1]; SZ[p] = src[2];
            }
            __syncthreads();

            int k = 0;
            for (; k + 4 <= m; k += 4) {
                // warp-uniform LDS.128 -> packed f32x2 component pairs
                ulonglong2 X = *(const ulonglong2*)(SX + k);
                ulonglong2 Y = *(const ulonglong2*)(SY + k);
                ulonglong2 Z = *(const ulonglong2*)(SZ + k);
                u64 nhA = fma2(Z.x, v2p, fma2(Y.x, v1p, mul2(X.x, v0p)));
                u64 nhB = fma2(Z.y, v2p, fma2(Y.y, v1p, mul2(X.y, v0p)));
                u64 fA  = fma2(nhA, c64p, c64p); // == (nh+1)*64 exactly
                u64 fB  = fma2(nhB, c64p, c64p);
                float f0, f1, f2, f3;
                unpack2(fA, f0, f1);
                unpack2(fB, f2, f3);
                u32 b0 = bin_clamp(f0), b1 = bin_clamp(f1);
                u32 b2 = bin_clamp(f2), b3 = bin_clamp(f3);
                // even -> HA, odd -> HB: two independent RMW chains
                u8* a0 = hA + (b0 >> 2) * 512 + (b0 & 3);
                u8* a1 = hB + (b1 >> 2) * 512 + (b1 & 3);
                u8* a2 = hA + (b2 >> 2) * 512 + (b2 & 3);
                u8* a3 = hB + (b3 >> 2) * 512 + (b3 & 3);
                *a0 = (u8)(*a0 + 1);
                *a1 = (u8)(*a1 + 1);
                *a2 = (u8)(*a2 + 1);
                *a3 = (u8)(*a3 + 1);
            }
            for (; k < m; ++k) {
                float nh = fmaf(SZ[k], v2, fmaf(SY[k], v1, __fmul_rn(SX[k], v0)));
                u32 bn = bin_clamp(fmaf(nh, 64.0f, 64.0f));
                u8* a = hA + (bn >> 2) * 512 + (bn & 3);
                *a = (u8)(*a + 1);
            }
            __syncthreads();
        }

        // flush: cumsum(HA+HB partial) += out[b][bin][t]; fully unrolled.
        // LDS word (bin>>2)*128 + t (bank t%32), REDG coalesced across t.
        {
            int acc = 0;
            u32* wa = (u32*)HA;
            u32* wb = (u32*)HB;
            float* dst = out + ((size_t)b * RR) * TT + t;
#pragma unroll
            for (int bin4 = 0; bin4 < RR / 4; ++bin4) {
                u32 a = wa[bin4 * 128 + t];
                u32 c = wb[bin4 * 128 + t];
                wa[bin4 * 128 + t] = 0u;         // rezero for next segment
                wb[bin4 * 128 + t] = 0u;
                acc += (int)(a & 255u) + (int)(c & 255u);
                atomicAdd(dst + (bin4 * 4 + 0) * TT, (float)acc);
                acc += (int)((a >> 8) & 255u) + (int)((c >> 8) & 255u);
                atomicAdd(dst + (bin4 * 4 + 1) * TT, (float)acc);
                acc += (int)((a >> 16) & 255u) + (int)((c >> 16) & 255u);
                atomicAdd(dst + (bin4 * 4 + 2) * TT, (float)acc);
                acc += (int)(a >> 24) + (int)(c >> 24);
                atomicAdd(dst + (bin4 * 4 + 3) * TT, (float)acc);
            }
        }
        pos = seg_end;
        __syncthreads();                         // protect stage/hist reuse
    }
}

extern "C" void kernel_launch(void* const* d_in, const int* in_sizes, int n_in,
                              void* d_out, int out_size) {
    const float* x     = (const float*)d_in[0];   // [200000, 3]
    const float* v     = (const float*)d_in[1];   // [3, 128]
    const int*   batch = (const int*)d_in[2];     // [200000], sorted
    const int n = in_sizes[2];

    float* out = (float*)d_out;                   // [64, 128, 128]
    const int n4 = out_size / 4;

    k_zero<<<(n4 + 255) / 256, 256>>>(out, n4);
    k_hist<<<NBLK, 128>>>(x, v, batch, n, out);
}

// round 11
// speedup vs baseline: 1.3242x; 1.1382x over previous
#include <cuda_runtime.h>

// FastECT: per-(batch,bin,theta) histogram + cumsum over bins.
// N=200000 pts (D=3), T=128 thetas, R=128 bins, B=64 batches, batch sorted.
//
// R11: the measured floor is smem MIO op count (LDS+STS RMW = 2 ops/update,
// ~25us). Replace the RMW with ONE red.shared.add.u32 (ATOMS, no return):
//  - same u8 packing, 4 bins/word/thread: word=(bin>>2)*128+t -> bank t%32
//    for any bin => perfectly bank-spread atomics, no conflicts.
//  - added value = 1 << ((bin&3)*8); per-byte counts <= 225 < 256 so no
//    carry crosses byte lanes. Thread t owns theta t -> its word anyway.
//  - no return value => no dependency chain at all; issue-bound only.
// __syncthreads() drains pending smem reductions before the flush.
// cumsum is linear => flush cumsum(partial) into d_out via f32 atomicAdd
// (exact integer adds, deterministic).

#define TT 128
#define RR 128
#define NBLK 888     // 148 SMs * 6 resident, single balanced wave
#define TILE 256     // points staged per tile (SoA)

typedef unsigned int       u32;
typedef unsigned char      u8;
typedef unsigned long long u64;

__device__ __forceinline__ int lower_bound_i32(const int* __restrict__ a, int n, int key) {
    int lo = 0, hi = n;
    while (lo < hi) {
        int mid = (lo + hi) >> 1;
        if (a[mid] < key) lo = mid + 1; else hi = mid;
    }
    return lo;
}

// packed f32x2 helpers (sm_103a): same per-lane rounding as scalar chain
__device__ __forceinline__ u64 pack2(float lo, float hi) {
    u64 r; asm("mov.b64 %0, {%1, %2};" : "=l"(r) : "f"(lo), "f"(hi)); return r;
}
__device__ __forceinline__ void unpack2(u64 v, float& lo, float& hi) {
    asm("mov.b64 {%0, %1}, %2;" : "=f"(lo), "=f"(hi) : "l"(v));
}
__device__ __forceinline__ u64 mul2(u64 a, u64 b) {
    u64 r; asm("mul.rn.f32x2 %0, %1, %2;" : "=l"(r) : "l"(a), "l"(b)); return r;
}
__device__ __forceinline__ u64 fma2(u64 a, u64 b, u64 c) {
    u64 r; asm("fma.rn.f32x2 %0, %1, %2, %3;" : "=l"(r) : "l"(a), "l"(b), "l"(c)); return r;
}

// bin = clip(floor(f), 0, 127) for f = 64*nh + 64:
// cvt.rzi.u32 saturates negatives to 0, floors positives; then min(.,127).
__device__ __forceinline__ u32 bin_clamp(float f) {
    return min(__float2uint_rz(f), 127u);
}

// fire-and-forget smem add (ATOMS.ADD no-return)
__device__ __forceinline__ void reds_add(u32 smem_addr, u32 val) {
    asm volatile("red.shared.add.u32 [%0], %1;" :: "r"(smem_addr), "r"(val) : "memory");
}

__global__ void __launch_bounds__(256)
k_zero(float* __restrict__ out, int n4) {
    int i = blockIdx.x * blockDim.x + threadIdx.x;
    if (i < n4) ((float4*)out)[i] = make_float4(0.f, 0.f, 0.f, 0.f);
}

__global__ void __launch_bounds__(128, 6)
k_hist(const float* __restrict__ x, const float* __restrict__ v,
       const int* __restrict__ batch, int n, float* __restrict__ out) {
    __shared__ u8 H[RR * TT];                    // u8, 4 bins/word/thread
    __shared__ float SX[TILE], SY[TILE], SZ[TILE];
    __shared__ int seg_end_sh;

    const int t = threadIdx.x;
    const int g = blockIdx.x;

    // 32-bit smem address of this thread's word base (H + t*4)
    const u32 hbase = (u32)__cvta_generic_to_shared(H) + ((u32)t << 2);

    const int lo = (int)(((long long)g)     * n / NBLK);
    const int hi = (int)(((long long)g + 1) * n / NBLK);

    const float v0 = v[t];
    const float v1 = v[TT + t];
    const float v2 = v[2 * TT + t];
    const u64 v0p = pack2(v0, v0), v1p = pack2(v1, v1), v2p = pack2(v2, v2);
    const u64 c64p = pack2(64.0f, 64.0f);

    // zero 16KB histogram (conflict-free uint4 stores)
    {
        uint4* a = (uint4*)H;
        for (int i = t; i < (RR * TT) / 16; i += 128)
            a[i] = make_uint4(0u, 0u, 0u, 0u);
    }

    int pos = lo;
    while (pos < hi) {
        if (t == 0) {
            int b = batch[pos];
            seg_end_sh = min(hi, lower_bound_i32(batch, n, b + 1));
        }
        __syncthreads();
        const int seg_end = seg_end_sh;
        const int b = batch[pos];                // uniform broadcast

        for (int base = pos; base < seg_end; base += TILE) {
            const int m = min(TILE, seg_end - base);
            for (int p = t; p < m; p += 128) {
                const float* src = x + (size_t)(base + p) * 3;
                SX[p] = src[0]; SY[p] = src[1]; SZ[p] = src[2];
            }
            __syncthreads();

            int k = 0;
            for (; k + 4 <= m; k += 4) {
                // warp-uniform LDS.128 -> packed f32x2 component pairs
                ulonglong2 X = *(const ulonglong2*)(SX + k);
                ulonglong2 Y = *(const ulonglong2*)(SY + k);
                ulonglong2 Z = *(const ulonglong2*)(SZ + k);
                u64 nhA = fma2(Z.x, v2p, fma2(Y.x, v1p, mul2(X.x, v0p)));
                u64 nhB = fma2(Z.y, v2p, fma2(Y.y, v1p, mul2(X.y, v0p)));
                u64 fA  = fma2(nhA, c64p, c64p); // == (nh+1)*64 exactly
                u64 fB  = fma2(nhB, c64p, c64p);
                float f0, f1, f2, f3;
                unpack2(fA, f0, f1);
                unpack2(fB, f2, f3);
                u32 b0 = bin_clamp(f0), b1 = bin_clamp(f1);
                u32 b2 = bin_clamp(f2), b3 = bin_clamp(f3);
                // one no-return smem reduction per update (bank t%32)
                reds_add(hbase + ((b0 >> 2) << 9), 1u << ((b0 & 3u) << 3));
                reds_add(hbase + ((b1 >> 2) << 9), 1u << ((b1 & 3u) << 3));
                reds_add(hbase + ((b2 >> 2) << 9), 1u << ((b2 & 3u) << 3));
                reds_add(hbase + ((b3 >> 2) << 9), 1u << ((b3 & 3u) << 3));
            }
            for (; k < m; ++k) {
                float nh = fmaf(SZ[k], v2, fmaf(SY[k], v1, __fmul_rn(SX[k], v0)));
                u32 bn = bin_clamp(fmaf(nh, 64.0f, 64.0f));
                reds_add(hbase + ((bn >> 2) << 9), 1u << ((bn & 3u) << 3));
            }
            __syncthreads();                     // drains pending reductions
        }

        // flush: cumsum(partial) += out[b][bin][t]; fully unrolled.
        // LDS word (bin>>2)*128 + t (bank t%32), REDG coalesced across t.
        {
            int acc = 0;
            u32* hw = (u32*)H;
            float* dst = out + ((size_t)b * RR) * TT + t;
#pragma unroll
            for (int bin4 = 0; bin4 < RR / 4; ++bin4) {
                u32 w = hw[bin4 * 128 + t];
                hw[bin4 * 128 + t] = 0u;         // rezero for next segment
                acc += (int)(w & 255u);
                atomicAdd(dst + (bin4 * 4 + 0) * TT, (float)acc);
                acc += (int)((w >> 8) & 255u);
                atomicAdd(dst + (bin4 * 4 + 1) * TT, (float)acc);
                acc += (int)((w >> 16) & 255u);
                atomicAdd(dst + (bin4 * 4 + 2) * TT, (float)acc);
                acc += (int)(w >> 24);
                atomicAdd(dst + (bin4 * 4 + 3) * TT, (float)acc);
            }
        }
        pos = seg_end;
        __syncthreads();                         // protect stage/hist reuse
    }
}

extern "C" void kernel_launch(void* const* d_in, const int* in_sizes, int n_in,
                              void* d_out, int out_size) {
    const float* x     = (const float*)d_in[0];   // [200000, 3]
    const float* v     = (const float*)d_in[1];   // [3, 128]
    const int*   batch = (const int*)d_in[2];     // [200000], sorted
    const int n = in_sizes[2];

    float* out = (float*)d_out;                   // [64, 128, 128]
    const int n4 = out_size / 4;

    k_zero<<<(n4 + 255) / 256, 256>>>(out, n4);
    k_hist<<<NBLK, 128>>>(x, v, batch, n, out);
}